// round 9
// baseline (speedup 1.0000x reference)
#include <cuda_runtime.h>
#include <cuda_bf16.h>
#include <math.h>

#define NN 50000
#define EE 800000
#define NEG_SLOPE 0.2f

// ---------------- scratch (no allocations allowed) ----------------
__device__ float g_ft[NN * 196];     // padded stride for layer 2 (196 = 49 float4)
__device__ float g_h[NN * 128];
__device__ float g_res2[NN * 194];
__device__ float g_el[NN * 2];
__device__ float g_er[NN * 2];
__device__ float g_denom[NN * 2];
__device__ float g_w[EE * 2];
__device__ int   g_deg[NN];
__device__ int   g_rowptr[NN + 1];
__device__ int   g_cursor[NN];
__device__ int   g_esrc[EE];

// ================= bf16x3 tensor-core GEMM (m16n8k16) =================
__device__ __forceinline__ unsigned pack_bf16x2(float x, float y) {
    __nv_bfloat162 t = __floats2bfloat162_rn(x, y);
    return *reinterpret_cast<unsigned*>(&t);
}

__device__ __forceinline__ void mma_bf16(float* c, const unsigned* a, const unsigned* b) {
    asm volatile(
        "mma.sync.aligned.m16n8k16.row.col.f32.bf16.bf16.f32 "
        "{%0,%1,%2,%3}, {%4,%5,%6,%7}, {%8,%9}, {%0,%1,%2,%3};\n"
        : "+f"(c[0]), "+f"(c[1]), "+f"(c[2]), "+f"(c[3])
        : "r"(a[0]), "r"(a[1]), "r"(a[2]), "r"(a[3]), "r"(b[0]), "r"(b[1]));
}

#define GBM 128
#define GBN 64
#define A_STR 68
#define B_STR 72
#define SM_AH 0
#define SM_AL (128 * A_STR)
#define SM_BH (2 * 128 * A_STR)
#define SM_BL (2 * 128 * A_STR + 64 * B_STR)
#define GEMM_SMEM_WORDS (2 * 128 * A_STR + 2 * 64 * B_STR)

// Dual-B: blocks with blockIdx.x >= gx use (B2 -> C2, ldc2).
__global__ void __launch_bounds__(256)
gemm_bf16(const float* __restrict__ A,
          const float* __restrict__ B1, float* __restrict__ C1, int ldc1,
          const float* __restrict__ B2, float* __restrict__ C2, int ldc2,
          int Nrows, int Mcols, int gx) {
    extern __shared__ unsigned smu[];
    unsigned* Ah = smu + SM_AH;
    unsigned* Al = smu + SM_AL;
    unsigned* Bh = smu + SM_BH;
    unsigned* Bl = smu + SM_BL;

    const int tid = threadIdx.x;
    const int lane = tid & 31;
    const int warp = tid >> 5;
    const int wm = warp & 3;
    const int wn = warp >> 2;
    const int row0 = blockIdx.y * GBM;
    const bool second = (blockIdx.x >= gx);
    const int bx = second ? (blockIdx.x - gx) : blockIdx.x;
    const float* B = second ? B2 : B1;
    float* C = second ? C2 : C1;
    const int ldc = second ? ldc2 : ldc1;
    const int col0 = bx * GBN;

    #pragma unroll 8
    for (int i = 0; i < 32; i++) {
        int e = tid + i * 256;
        int r = e >> 6;
        int kp = e & 63;
        int gr = row0 + r;
        float2 v = make_float2(0.f, 0.f);
        if (gr < Nrows) v = *(const float2*)(A + (long)gr * 128 + kp * 2);
        float hx = __bfloat162float(__float2bfloat16_rn(v.x));
        float hy = __bfloat162float(__float2bfloat16_rn(v.y));
        Ah[r * A_STR + kp] = pack_bf16x2(hx, hy);
        Al[r * A_STR + kp] = pack_bf16x2(v.x - hx, v.y - hy);
    }
    #pragma unroll 4
    for (int i = 0; i < 16; i++) {
        int e = tid + i * 256;
        int c = e & 63;
        int kp = e >> 6;
        int gc = col0 + c;
        float v0 = 0.f, v1 = 0.f;
        if (gc < Mcols) {
            v0 = B[(2 * kp) * Mcols + gc];
            v1 = B[(2 * kp + 1) * Mcols + gc];
        }
        float h0 = __bfloat162float(__float2bfloat16_rn(v0));
        float h1 = __bfloat162float(__float2bfloat16_rn(v1));
        Bh[kp * B_STR + c] = pack_bf16x2(h0, h1);
        Bl[kp * B_STR + c] = pack_bf16x2(v0 - h0, v1 - h1);
    }
    __syncthreads();

    float acc[2][4][4];
    #pragma unroll
    for (int mt = 0; mt < 2; mt++)
        #pragma unroll
        for (int nt = 0; nt < 4; nt++)
            #pragma unroll
            for (int j = 0; j < 4; j++) acc[mt][nt][j] = 0.f;

    const int qr = lane >> 2;
    const int qc = lane & 3;

    #pragma unroll
    for (int ks = 0; ks < 8; ks++) {
        const int kg = ks * 8;
        unsigned aH[2][4], aL[2][4];
        #pragma unroll
        for (int mt = 0; mt < 2; mt++) {
            int r = wm * 32 + mt * 16 + qr;
            int b0 = r * A_STR + kg + qc;
            int b1 = (r + 8) * A_STR + kg + qc;
            aH[mt][0] = Ah[b0];     aH[mt][1] = Ah[b1];
            aH[mt][2] = Ah[b0 + 4]; aH[mt][3] = Ah[b1 + 4];
            aL[mt][0] = Al[b0];     aL[mt][1] = Al[b1];
            aL[mt][2] = Al[b0 + 4]; aL[mt][3] = Al[b1 + 4];
        }
        unsigned bH[4][2], bL[4][2];
        #pragma unroll
        for (int nt = 0; nt < 4; nt++) {
            int c = wn * 32 + nt * 8 + qr;
            int b0 = (kg + qc) * B_STR + c;
            int b1 = (kg + qc + 4) * B_STR + c;
            bH[nt][0] = Bh[b0]; bH[nt][1] = Bh[b1];
            bL[nt][0] = Bl[b0]; bL[nt][1] = Bl[b1];
        }
        #pragma unroll
        for (int mt = 0; mt < 2; mt++)
            #pragma unroll
            for (int nt = 0; nt < 4; nt++) {
                mma_bf16(acc[mt][nt], aH[mt], bH[nt]);
                mma_bf16(acc[mt][nt], aH[mt], bL[nt]);
                mma_bf16(acc[mt][nt], aL[mt], bH[nt]);
            }
    }

    #pragma unroll
    for (int mt = 0; mt < 2; mt++) {
        int r = row0 + wm * 32 + mt * 16 + qr;
        #pragma unroll
        for (int nt = 0; nt < 4; nt++) {
            int c = col0 + wn * 32 + nt * 8 + qc * 2;
            if (r < Nrows) {
                if (c < Mcols)     C[(long)r * ldc + c]     = acc[mt][nt][0];
                if (c + 1 < Mcols) C[(long)r * ldc + c + 1] = acc[mt][nt][1];
            }
            if (r + 8 < Nrows) {
                if (c < Mcols)     C[(long)(r + 8) * ldc + c]     = acc[mt][nt][2];
                if (c + 1 < Mcols) C[(long)(r + 8) * ldc + c + 1] = acc[mt][nt][3];
            }
        }
    }
}

// ---------------- CSR build ----------------
__global__ void zero_deg(int* __restrict__ deg, int n) {
    int i = blockIdx.x * blockDim.x + threadIdx.x;
    if (i < n) deg[i] = 0;
}

__global__ void hist_dst(const int* __restrict__ dst, int* __restrict__ deg, int E) {
    int e = blockIdx.x * blockDim.x + threadIdx.x;
    if (e < E) atomicAdd(&deg[dst[e]], 1);
}

__global__ void exscan_kernel(const int* __restrict__ deg, int* __restrict__ rowptr,
                              int* __restrict__ cursor, int n) {
    __shared__ int sh[1024];
    int t = threadIdx.x;
    const int CH = (n + 1023) / 1024;
    int base = t * CH;
    int sum = 0;
    for (int i = 0; i < CH; i++) {
        int idx = base + i;
        if (idx < n) sum += deg[idx];
    }
    sh[t] = sum;
    __syncthreads();
    for (int off = 1; off < 1024; off <<= 1) {
        int v = (t >= off) ? sh[t - off] : 0;
        __syncthreads();
        sh[t] += v;
        __syncthreads();
    }
    int run = (t == 0) ? 0 : sh[t - 1];
    for (int i = 0; i < CH; i++) {
        int idx = base + i;
        if (idx < n) {
            rowptr[idx] = run;
            cursor[idx] = run;
            run += deg[idx];
        }
    }
    if (t == 1023) rowptr[n] = sh[1023];
}

__global__ void fill_csr(const int* __restrict__ src, const int* __restrict__ dst,
                         int* __restrict__ cursor, int* __restrict__ esrc, int E) {
    int e = blockIdx.x * blockDim.x + threadIdx.x;
    if (e >= E) return;
    int pos = atomicAdd(&cursor[dst[e]], 1);
    esrc[pos] = src[e];
}

// ---------------- el/er: warp per node, coalesced (strided ft) ----------------
__global__ void el_er_warp(const float* __restrict__ ft,
                           const float* __restrict__ al, const float* __restrict__ ar,
                           float* __restrict__ el, float* __restrict__ er,
                           int N, int D, int stride) {
    int warp = (blockIdx.x * blockDim.x + threadIdx.x) >> 5;
    int lane = threadIdx.x & 31;
    if (warp >= N) return;
    int F = 2 * D;
    const float* f = ft + (long)warp * stride;
    float sl0 = 0.f, sr0 = 0.f, sl1 = 0.f, sr1 = 0.f;
    for (int i = lane; i < F; i += 32) {
        float v = f[i];
        float a = al[i];
        float r = ar[i];
        if (i < D) { sl0 += v * a; sr0 += v * r; }
        else       { sl1 += v * a; sr1 += v * r; }
    }
    #pragma unroll
    for (int o = 16; o > 0; o >>= 1) {
        sl0 += __shfl_xor_sync(0xffffffff, sl0, o);
        sr0 += __shfl_xor_sync(0xffffffff, sr0, o);
        sl1 += __shfl_xor_sync(0xffffffff, sl1, o);
        sr1 += __shfl_xor_sync(0xffffffff, sr1, o);
    }
    if (lane == 0) {
        el[warp * 2]     = sl0;
        el[warp * 2 + 1] = sl1;
        er[warp * 2]     = sr0;
        er[warp * 2 + 1] = sr1;
    }
}

// ---------------- single-pass softmax: warp per node ----------------
__global__ void node_softmax(const int* __restrict__ rowptr, const int* __restrict__ esrc,
                             const float* __restrict__ el, const float* __restrict__ er,
                             float* __restrict__ w, float* __restrict__ denom, int N) {
    int warp = (blockIdx.x * blockDim.x + threadIdx.x) >> 5;
    int lane = threadIdx.x & 31;
    if (warp >= N) return;
    int start = rowptr[warp], end = rowptr[warp + 1];
    float er0 = er[warp * 2], er1 = er[warp * 2 + 1];

    float s0 = 0.f, s1 = 0.f;
    for (int i = start + lane; i < end; i += 32) {
        int s = esrc[i];
        float v0 = el[s * 2] + er0;     v0 = (v0 > 0.f) ? v0 : NEG_SLOPE * v0;
        float v1 = el[s * 2 + 1] + er1; v1 = (v1 > 0.f) ? v1 : NEG_SLOPE * v1;
        float e0 = __expf(v0), e1 = __expf(v1);
        w[i * 2] = e0; w[i * 2 + 1] = e1;
        s0 += e0; s1 += e1;
    }
    #pragma unroll
    for (int o = 16; o > 0; o >>= 1) {
        s0 += __shfl_xor_sync(0xffffffff, s0, o);
        s1 += __shfl_xor_sync(0xffffffff, s1, o);
    }
    if (lane == 0) {
        denom[warp * 2]     = s0;
        denom[warp * 2 + 1] = s1;
    }
}

// ---------------- aggregation: 4 warps split edges, float4 gathers ----------------
// Each warp handles every 4th edge; lane = float4 chunk of the source row.
// mode: 0 = ELU (out compact F), 2 = mean-over-heads + drop-last-node.
__global__ void __launch_bounds__(128)
node_aggregate(const int* __restrict__ rowptr, const int* __restrict__ esrc,
               const float4* __restrict__ ftv, const float* __restrict__ w,
               const float* __restrict__ denom,
               const float* __restrict__ bias, const float* __restrict__ res,
               float* __restrict__ out, int F, int D, int stride4, int mode) {
    __shared__ float s_red[4 * 256];
    __shared__ float s_fin[224];

    const int n = blockIdx.x;
    const int tid = threadIdx.x;
    const int wid = tid >> 5;
    const int lane = tid & 31;
    const int start = rowptr[n], end = rowptr[n + 1];
    const int CHN = (F + 3) >> 2;           // float4 chunks per row (32 or 49)
    const bool second = (lane + 32) < CHN;

    const int c0 = lane * 4;
    const int c1 = 128 + lane * 4;

    float4 a0 = make_float4(0.f, 0.f, 0.f, 0.f);
    float4 a1 = make_float4(0.f, 0.f, 0.f, 0.f);

    #pragma unroll 2
    for (int i = start + wid; i < end; i += 4) {
        int s = esrc[i];
        float2 e = *(const float2*)(w + i * 2);
        const float4* row = ftv + (long)s * stride4;
        float4 f0 = row[lane];
        a0.x += f0.x * ((c0 + 0 < D) ? e.x : e.y);
        a0.y += f0.y * ((c0 + 1 < D) ? e.x : e.y);
        a0.z += f0.z * ((c0 + 2 < D) ? e.x : e.y);
        a0.w += f0.w * ((c0 + 3 < D) ? e.x : e.y);
        if (second) {
            float4 f1 = row[lane + 32];
            a1.x += f1.x * ((c1 + 0 < D) ? e.x : e.y);
            a1.y += f1.y * ((c1 + 1 < D) ? e.x : e.y);
            a1.z += f1.z * ((c1 + 2 < D) ? e.x : e.y);
            a1.w += f1.w * ((c1 + 3 < D) ? e.x : e.y);
        }
    }

    *(float4*)(s_red + wid * 256 + lane * 4) = a0;
    if (second) *(float4*)(s_red + wid * 256 + 128 + lane * 4) = a1;
    __syncthreads();

    for (int ch = tid; ch < F; ch += 128) {
        float sum = s_red[ch] + s_red[256 + ch] + s_red[512 + ch] + s_red[768 + ch];
        int h = (ch >= D) ? 1 : 0;
        float dn = denom[n * 2 + h];
        float r = sum * ((dn > 0.f) ? (1.f / dn) : 0.f) + bias[ch];
        if (res) r += res[(long)n * F + ch];
        if (mode == 0) {
            r = (r > 0.f) ? r : (__expf(r) - 1.f);
            out[(long)n * F + ch] = r;
        } else {
            s_fin[ch] = r;
        }
    }
    if (mode == 2) {
        __syncthreads();
        if (tid < D && n < NN - 1)
            out[(long)n * D + tid] = 0.5f * (s_fin[tid] + s_fin[tid + D]);
    }
}

// ---------------- host-side orchestration ----------------
static inline int divup(int a, int b) { return (a + b - 1) / b; }

struct Scratch {
    float *ft, *h, *res2, *el, *er, *denom, *w;
    int *deg, *rowptr, *cursor, *esrc;
};

static void get_scratch(Scratch& s) {
    cudaGetSymbolAddress((void**)&s.ft, g_ft);
    cudaGetSymbolAddress((void**)&s.h, g_h);
    cudaGetSymbolAddress((void**)&s.res2, g_res2);
    cudaGetSymbolAddress((void**)&s.el, g_el);
    cudaGetSymbolAddress((void**)&s.er, g_er);
    cudaGetSymbolAddress((void**)&s.denom, g_denom);
    cudaGetSymbolAddress((void**)&s.w, g_w);
    cudaGetSymbolAddress((void**)&s.deg, g_deg);
    cudaGetSymbolAddress((void**)&s.rowptr, g_rowptr);
    cudaGetSymbolAddress((void**)&s.cursor, g_cursor);
    cudaGetSymbolAddress((void**)&s.esrc, g_esrc);
}

static void launch_gemm(const float* A, const float* B1, float* C1, int ldc1,
                        const float* B2, float* C2, int ldc2, int Nrows, int Mcols) {
    const int smem_bytes = GEMM_SMEM_WORDS * 4;
    cudaFuncSetAttribute(gemm_bf16, cudaFuncAttributeMaxDynamicSharedMemorySize, smem_bytes);
    int gx = divup(Mcols, GBN);
    int total_gx = (B2 != nullptr) ? 2 * gx : gx;
    dim3 grid(total_gx, divup(Nrows, GBM));
    gemm_bf16<<<grid, 256, smem_bytes>>>(A, B1, C1, ldc1, B2, C2, ldc2, Nrows, Mcols, gx);
}

extern "C" void kernel_launch(void* const* d_in, const int* in_sizes, int n_in,
                              void* d_out, int out_size) {
    const float* x      = (const float*)d_in[0];
    const int*   src    = (const int*)d_in[1];
    const int*   dst    = (const int*)d_in[2];
    const float* W0     = (const float*)d_in[3];
    const float* al0    = (const float*)d_in[4];
    const float* ar0    = (const float*)d_in[5];
    const float* b0     = (const float*)d_in[6];
    const float* W1     = (const float*)d_in[7];
    const float* al1    = (const float*)d_in[8];
    const float* ar1    = (const float*)d_in[9];
    const float* b1     = (const float*)d_in[10];
    const float* W2     = (const float*)d_in[11];
    const float* al2    = (const float*)d_in[12];
    const float* ar2    = (const float*)d_in[13];
    const float* b2     = (const float*)d_in[14];
    const float* res_W2 = (const float*)d_in[15];
    float* out = (float*)d_out;

    Scratch s;
    get_scratch(s);

    const int N = NN, E = EE;
    const float4* ftv = (const float4*)s.ft;

    // ---- layer 0 (el_er in profiled slot 4) ----
    zero_deg<<<divup(N, 256), 256>>>(s.deg, N);                          // 1
    hist_dst<<<divup(E, 256), 256>>>(dst, s.deg, E);                     // 2
    launch_gemm(x, W0, s.ft, 128, nullptr, nullptr, 0, N, 128);          // 3
    el_er_warp<<<divup(N * 32, 256), 256>>>(s.ft, al0, ar0, s.el, s.er, N, 64, 128);  // 4
    exscan_kernel<<<1, 1024>>>(s.deg, s.rowptr, s.cursor, N);            // 5
    fill_csr<<<divup(E, 256), 256>>>(src, dst, s.cursor, s.esrc, E);     // 6
    node_softmax<<<divup(N * 32, 256), 256>>>(s.rowptr, s.esrc, s.el, s.er, s.w, s.denom, N);
    node_aggregate<<<N, 128>>>(s.rowptr, s.esrc, ftv, s.w, s.denom, b0, nullptr,
                               s.h, 128, 64, 32, 0);

    // ---- layer 1: identity residual, ELU ----
    launch_gemm(s.h, W1, s.ft, 128, nullptr, nullptr, 0, N, 128);
    el_er_warp<<<divup(N * 32, 256), 256>>>(s.ft, al1, ar1, s.el, s.er, N, 64, 128);
    node_softmax<<<divup(N * 32, 256), 256>>>(s.rowptr, s.esrc, s.el, s.er, s.w, s.denom, N);
    node_aggregate<<<N, 128>>>(s.rowptr, s.esrc, ftv, s.w, s.denom, b1, s.h,
                               s.h, 128, 64, 32, 0);

    // ---- layer 2: dual GEMM (W2 -> ft stride 196, res_W2 -> res2 compact) ----
    launch_gemm(s.h, W2, s.ft, 196, res_W2, s.res2, 194, N, 194);
    el_er_warp<<<divup(N * 32, 256), 256>>>(s.ft, al2, ar2, s.el, s.er, N, 97, 196);
    node_softmax<<<divup(N * 32, 256), 256>>>(s.rowptr, s.esrc, s.el, s.er, s.w, s.denom, N);
    node_aggregate<<<N, 128>>>(s.rowptr, s.esrc, ftv, s.w, s.denom, b2, s.res2,
                               out, 194, 97, 49, 2);
}

// round 10
// speedup vs baseline: 1.0377x; 1.0377x over previous
#include <cuda_runtime.h>
#include <cuda_bf16.h>
#include <math.h>

#define NN 50000
#define EE 800000
#define NEG_SLOPE 0.2f

// ---------------- scratch (no allocations allowed) ----------------
__device__ float    g_ft[NN * 196];     // stride 128 (layers 0/1) or 196 (layer 2)
__device__ float    g_h[NN * 128];
__device__ float    g_res2[NN * 194];
__device__ float    g_el[NN * 2];
__device__ float    g_er[NN * 2];
__device__ unsigned g_ah[NN * 64];      // prepacked A hi (bf16x2 per kpair)
__device__ unsigned g_al[NN * 64];      // prepacked A lo
__device__ unsigned g_bh[2 * 64 * 256]; // prepacked B hi, 2 regions [kp][256]
__device__ unsigned g_bl[2 * 64 * 256];
__device__ int      g_deg[NN];
__device__ int      g_rowptr[NN + 1];
__device__ int      g_cursor[NN];
__device__ int      g_esrc[EE];

#define BP_STR 256
#define BP_REGION (64 * BP_STR)

// ---------------- bf16 helpers ----------------
__device__ __forceinline__ unsigned pack_bf16x2(float x, float y) {
    __nv_bfloat162 t = __floats2bfloat162_rn(x, y);
    return *reinterpret_cast<unsigned*>(&t);
}

__device__ __forceinline__ void mma_bf16(float* c, const unsigned* a, const unsigned* b) {
    asm volatile(
        "mma.sync.aligned.m16n8k16.row.col.f32.bf16.bf16.f32 "
        "{%0,%1,%2,%3}, {%4,%5,%6,%7}, {%8,%9}, {%0,%1,%2,%3};\n"
        : "+f"(c[0]), "+f"(c[1]), "+f"(c[2]), "+f"(c[3])
        : "r"(a[0]), "r"(a[1]), "r"(a[2]), "r"(a[3]), "r"(b[0]), "r"(b[1]));
}

// ---------------- prepack kernels ----------------
// A [Nrows,128] fp32 -> hi/lo bf16x2 at [row*64 + kpair]
__global__ void prepack_A(const float* __restrict__ A,
                          unsigned* __restrict__ ah, unsigned* __restrict__ al, int total) {
    int idx = blockIdx.x * blockDim.x + threadIdx.x;   // over Nrows*64
    if (idx >= total) return;
    float2 v = *(const float2*)(A + (long)idx * 2);
    float hx = __bfloat162float(__float2bfloat16_rn(v.x));
    float hy = __bfloat162float(__float2bfloat16_rn(v.y));
    ah[idx] = pack_bf16x2(hx, hy);
    al[idx] = pack_bf16x2(v.x - hx, v.y - hy);
}

// B [128,M] fp32 -> region r: [kp][BP_STR] hi/lo (zero-padded to BP_STR cols)
__global__ void prepack_B(const float* __restrict__ B1, const float* __restrict__ B2,
                          unsigned* __restrict__ bh, unsigned* __restrict__ bl,
                          int M, int nregions) {
    int idx = blockIdx.x * blockDim.x + threadIdx.x;
    int total = nregions * BP_REGION;
    if (idx >= total) return;
    int region = idx / BP_REGION;
    int rem = idx - region * BP_REGION;
    int kp = rem / BP_STR;
    int c = rem - kp * BP_STR;
    const float* B = region ? B2 : B1;
    float v0 = 0.f, v1 = 0.f;
    if (c < M) {
        v0 = B[(2 * kp) * M + c];
        v1 = B[(2 * kp + 1) * M + c];
    }
    float h0 = __bfloat162float(__float2bfloat16_rn(v0));
    float h1 = __bfloat162float(__float2bfloat16_rn(v1));
    bh[idx] = pack_bf16x2(h0, h1);
    bl[idx] = pack_bf16x2(v0 - h0, v1 - h1);
}

// ================= bf16x3 GEMM, 128x128 tile, prepacked operands =================
#define GBM 128
#define GBN 128
#define A_STR 68           // 68 mod 32 == 4 -> conflict-free A frag reads
#define B_STR 136          // 136 mod 32 == 8 -> conflict-free B frag reads
#define SM_AH 0
#define SM_AL (128 * A_STR)
#define SM_BH (2 * 128 * A_STR)
#define SM_BL (2 * 128 * A_STR + 64 * B_STR)
#define GEMM_SMEM_WORDS (2 * 128 * A_STR + 2 * 64 * B_STR)   // 34816 u32 = 139264 B

// Dual-C: blocks with blockIdx.x >= gx use B-region 1 -> (C2, ldc2).
__global__ void __launch_bounds__(256)
gemm_bf16(const unsigned* __restrict__ gah, const unsigned* __restrict__ gal,
          const unsigned* __restrict__ bph, const unsigned* __restrict__ bpl,
          float* __restrict__ C1, int ldc1, float* __restrict__ C2, int ldc2,
          int Nrows, int Mcols, int gx) {
    extern __shared__ unsigned smu[];
    unsigned* Ah = smu + SM_AH;
    unsigned* Al = smu + SM_AL;
    unsigned* Bh = smu + SM_BH;
    unsigned* Bl = smu + SM_BL;

    const int tid = threadIdx.x;
    const int lane = tid & 31;
    const int warp = tid >> 5;
    const int wm = warp & 3;       // 4 warps along M (32 rows each)
    const int wn = warp >> 2;      // 2 warps along N (64 cols each)
    const int row0 = blockIdx.y * GBM;
    const bool second = (blockIdx.x >= gx);
    const int bx = second ? (blockIdx.x - gx) : blockIdx.x;
    float* C = second ? C2 : C1;
    const int ldc = second ? ldc2 : ldc1;
    const int col0 = bx * GBN;
    const unsigned* bhs = bph + (second ? BP_REGION : 0);
    const unsigned* bls = bpl + (second ? BP_REGION : 0);

    // A smem: [r][kp], pure copy of prepacked
    #pragma unroll 8
    for (int i = 0; i < 32; i++) {
        int e = tid + i * 256;
        int r = e >> 6;
        int kp = e & 63;
        int gr = row0 + r;
        unsigned h = 0, l = 0;
        if (gr < Nrows) {
            h = gah[(long)gr * 64 + kp];
            l = gal[(long)gr * 64 + kp];
        }
        Ah[r * A_STR + kp] = h;
        Al[r * A_STR + kp] = l;
    }
    // B smem: [kp][c] for cols [col0, col0+128)
    #pragma unroll 8
    for (int i = 0; i < 32; i++) {
        int e = tid + i * 256;
        int c = e & 127;
        int kp = e >> 7;
        Bh[kp * B_STR + c] = bhs[kp * BP_STR + col0 + c];
        Bl[kp * B_STR + c] = bls[kp * BP_STR + col0 + c];
    }
    __syncthreads();

    float acc[2][8][4];
    #pragma unroll
    for (int mt = 0; mt < 2; mt++)
        #pragma unroll
        for (int nt = 0; nt < 8; nt++)
            #pragma unroll
            for (int j = 0; j < 4; j++) acc[mt][nt][j] = 0.f;

    const int qr = lane >> 2;
    const int qc = lane & 3;

    #pragma unroll
    for (int ks = 0; ks < 8; ks++) {
        const int kg = ks * 8;
        unsigned aH[2][4], aL[2][4];
        #pragma unroll
        for (int mt = 0; mt < 2; mt++) {
            int r = wm * 32 + mt * 16 + qr;
            int b0 = r * A_STR + kg + qc;
            int b1 = (r + 8) * A_STR + kg + qc;
            aH[mt][0] = Ah[b0];     aH[mt][1] = Ah[b1];
            aH[mt][2] = Ah[b0 + 4]; aH[mt][3] = Ah[b1 + 4];
            aL[mt][0] = Al[b0];     aL[mt][1] = Al[b1];
            aL[mt][2] = Al[b0 + 4]; aL[mt][3] = Al[b1 + 4];
        }
        #pragma unroll
        for (int nt = 0; nt < 8; nt++) {
            int c = wn * 64 + nt * 8 + qr;
            int b0 = (kg + qc) * B_STR + c;
            int b1 = (kg + qc + 4) * B_STR + c;
            unsigned bH[2] = { Bh[b0], Bh[b1] };
            unsigned bL[2] = { Bl[b0], Bl[b1] };
            #pragma unroll
            for (int mt = 0; mt < 2; mt++) {
                mma_bf16(acc[mt][nt], aH[mt], bH);
                mma_bf16(acc[mt][nt], aH[mt], bL);
                mma_bf16(acc[mt][nt], aL[mt], bH);
            }
        }
    }

    #pragma unroll
    for (int mt = 0; mt < 2; mt++) {
        int r = row0 + wm * 32 + mt * 16 + qr;
        #pragma unroll
        for (int nt = 0; nt < 8; nt++) {
            int c = col0 + wn * 64 + nt * 8 + qc * 2;
            if (r < Nrows) {
                if (c < Mcols)     C[(long)r * ldc + c]     = acc[mt][nt][0];
                if (c + 1 < Mcols) C[(long)r * ldc + c + 1] = acc[mt][nt][1];
            }
            if (r + 8 < Nrows) {
                if (c < Mcols)     C[(long)(r + 8) * ldc + c]     = acc[mt][nt][2];
                if (c + 1 < Mcols) C[(long)(r + 8) * ldc + c + 1] = acc[mt][nt][3];
            }
        }
    }
}

// ---------------- CSR build ----------------
__global__ void zero_deg(int* __restrict__ deg, int n) {
    int i = blockIdx.x * blockDim.x + threadIdx.x;
    if (i < n) deg[i] = 0;
}

__global__ void hist_dst(const int* __restrict__ dst, int* __restrict__ deg, int E) {
    int e = blockIdx.x * blockDim.x + threadIdx.x;
    if (e < E) atomicAdd(&deg[dst[e]], 1);
}

__global__ void exscan_kernel(const int* __restrict__ deg, int* __restrict__ rowptr,
                              int* __restrict__ cursor, int n) {
    __shared__ int sh[1024];
    int t = threadIdx.x;
    const int CH = (n + 1023) / 1024;
    int base = t * CH;
    int sum = 0;
    for (int i = 0; i < CH; i++) {
        int idx = base + i;
        if (idx < n) sum += deg[idx];
    }
    sh[t] = sum;
    __syncthreads();
    for (int off = 1; off < 1024; off <<= 1) {
        int v = (t >= off) ? sh[t - off] : 0;
        __syncthreads();
        sh[t] += v;
        __syncthreads();
    }
    int run = (t == 0) ? 0 : sh[t - 1];
    for (int i = 0; i < CH; i++) {
        int idx = base + i;
        if (idx < n) {
            rowptr[idx] = run;
            cursor[idx] = run;
            run += deg[idx];
        }
    }
    if (t == 1023) rowptr[n] = sh[1023];
}

__global__ void fill_csr(const int* __restrict__ src, const int* __restrict__ dst,
                         int* __restrict__ cursor, int* __restrict__ esrc, int E) {
    int e = blockIdx.x * blockDim.x + threadIdx.x;
    if (e >= E) return;
    int pos = atomicAdd(&cursor[dst[e]], 1);
    esrc[pos] = src[e];
}

// ---------------- el/er: warp per node ----------------
__global__ void el_er_warp(const float* __restrict__ ft,
                           const float* __restrict__ al, const float* __restrict__ ar,
                           float* __restrict__ el, float* __restrict__ er,
                           int N, int D, int stride) {
    int warp = (blockIdx.x * blockDim.x + threadIdx.x) >> 5;
    int lane = threadIdx.x & 31;
    if (warp >= N) return;
    int F = 2 * D;
    const float* f = ft + (long)warp * stride;
    float sl0 = 0.f, sr0 = 0.f, sl1 = 0.f, sr1 = 0.f;
    for (int i = lane; i < F; i += 32) {
        float v = f[i];
        float a = al[i];
        float r = ar[i];
        if (i < D) { sl0 += v * a; sr0 += v * r; }
        else       { sl1 += v * a; sr1 += v * r; }
    }
    #pragma unroll
    for (int o = 16; o > 0; o >>= 1) {
        sl0 += __shfl_xor_sync(0xffffffff, sl0, o);
        sr0 += __shfl_xor_sync(0xffffffff, sr0, o);
        sl1 += __shfl_xor_sync(0xffffffff, sl1, o);
        sr1 += __shfl_xor_sync(0xffffffff, sr1, o);
    }
    if (lane == 0) {
        el[warp * 2]     = sl0;
        el[warp * 2 + 1] = sl1;
        er[warp * 2]     = sr0;
        er[warp * 2 + 1] = sr1;
    }
}

// ---------------- fused softmax + aggregate: warp per node ----------------
// One pass: lanes compute exp(leaky(...)) for 32 edges at a time (once per
// edge), shfl-broadcast weight+src to the whole warp for the float4 gather.
// Unnormalized accumulation; scale by 1/denom at the end (shift-invariant).
// mode: 0 = ELU (out stride F, float4), 2 = mean-over-heads + drop-last-node.
__global__ void __launch_bounds__(256)
gat_agg_fused(const int* __restrict__ rowptr, const int* __restrict__ esrc,
              const float4* __restrict__ ftv,
              const float* __restrict__ el, const float* __restrict__ er,
              const float* __restrict__ bias, const float* __restrict__ res,
              float* __restrict__ out, int F, int D, int stride4, int mode) {
    __shared__ float s_fin[8][194];
    const int wid = threadIdx.x >> 5;
    const int lane = threadIdx.x & 31;
    const int n = blockIdx.x * 8 + wid;
    if (n >= NN) return;

    const int start = rowptr[n], end = rowptr[n + 1];
    const float er0 = er[n * 2], er1 = er[n * 2 + 1];
    const int CHN = (F + 3) >> 2;
    const bool secondc = (lane + 32) < CHN;
    const int c0 = lane * 4;
    const int c1 = 128 + lane * 4;

    float4 a0 = make_float4(0.f, 0.f, 0.f, 0.f);
    float4 a1 = make_float4(0.f, 0.f, 0.f, 0.f);
    float accw0 = 0.f, accw1 = 0.f;

    for (int base = start; base < end; base += 32) {
        int i = base + lane;
        int s = 0;
        float e0 = 0.f, e1 = 0.f;
        if (i < end) {
            s = esrc[i];
            float v0 = el[s * 2] + er0;     v0 = (v0 > 0.f) ? v0 : NEG_SLOPE * v0;
            float v1 = el[s * 2 + 1] + er1; v1 = (v1 > 0.f) ? v1 : NEG_SLOPE * v1;
            e0 = __expf(v0);
            e1 = __expf(v1);
        }
        accw0 += e0;
        accw1 += e1;
        int cnt = min(32, end - base);
        #pragma unroll 4
        for (int j = 0; j < cnt; j++) {
            float w0 = __shfl_sync(0xffffffff, e0, j);
            float w1 = __shfl_sync(0xffffffff, e1, j);
            int sj   = __shfl_sync(0xffffffff, s, j);
            const float4* row = ftv + (long)sj * stride4;
            float4 f0 = row[lane];
            a0.x += f0.x * ((c0 + 0 < D) ? w0 : w1);
            a0.y += f0.y * ((c0 + 1 < D) ? w0 : w1);
            a0.z += f0.z * ((c0 + 2 < D) ? w0 : w1);
            a0.w += f0.w * ((c0 + 3 < D) ? w0 : w1);
            if (secondc) {
                float4 f1 = row[lane + 32];
                a1.x += f1.x * ((c1 + 0 < D) ? w0 : w1);
                a1.y += f1.y * ((c1 + 1 < D) ? w0 : w1);
                a1.z += f1.z * ((c1 + 2 < D) ? w0 : w1);
                a1.w += f1.w * ((c1 + 3 < D) ? w0 : w1);
            }
        }
    }

    #pragma unroll
    for (int o = 16; o > 0; o >>= 1) {
        accw0 += __shfl_xor_sync(0xffffffff, accw0, o);
        accw1 += __shfl_xor_sync(0xffffffff, accw1, o);
    }
    const float inv0 = (accw0 > 0.f) ? (1.f / accw0) : 0.f;
    const float inv1 = (accw1 > 0.f) ? (1.f / accw1) : 0.f;

    if (mode == 0) {
        // F = 128: one float4 per lane; bias/res aligned
        float4 b4 = *(const float4*)(bias + c0);
        float4 r;
        r.x = a0.x * ((c0 + 0 < D) ? inv0 : inv1) + b4.x;
        r.y = a0.y * ((c0 + 1 < D) ? inv0 : inv1) + b4.y;
        r.z = a0.z * ((c0 + 2 < D) ? inv0 : inv1) + b4.z;
        r.w = a0.w * ((c0 + 3 < D) ? inv0 : inv1) + b4.w;
        if (res) {
            float4 rv = *(const float4*)(res + (long)n * F + c0);
            r.x += rv.x; r.y += rv.y; r.z += rv.z; r.w += rv.w;
        }
        r.x = (r.x > 0.f) ? r.x : (__expf(r.x) - 1.f);
        r.y = (r.y > 0.f) ? r.y : (__expf(r.y) - 1.f);
        r.z = (r.z > 0.f) ? r.z : (__expf(r.z) - 1.f);
        r.w = (r.w > 0.f) ? r.w : (__expf(r.w) - 1.f);
        *(float4*)(out + (long)n * F + c0) = r;
    } else {
        // F = 194, D = 97: scale+bias+res per channel into smem, then head-mean
        float v0[4] = {a0.x, a0.y, a0.z, a0.w};
        float v1[4] = {a1.x, a1.y, a1.z, a1.w};
        #pragma unroll
        for (int jj = 0; jj < 4; jj++) {
            int ch = c0 + jj;
            float r = v0[jj] * ((ch < D) ? inv0 : inv1) + bias[ch];
            if (res) r += res[(long)n * F + ch];
            s_fin[wid][ch] = r;
        }
        if (secondc) {
            #pragma unroll
            for (int jj = 0; jj < 4; jj++) {
                int ch = c1 + jj;
                if (ch < F) {
                    float r = v1[jj] * ((ch < D) ? inv0 : inv1) + bias[ch];
                    if (res) r += res[(long)n * F + ch];
                    s_fin[wid][ch] = r;
                }
            }
        }
        __syncwarp();
        if (n < NN - 1) {
            for (int c = lane; c < 97; c += 32)
                out[(long)n * 97 + c] = 0.5f * (s_fin[wid][c] + s_fin[wid][c + 97]);
        }
    }
}

// ---------------- host-side orchestration ----------------
static inline int divup(int a, int b) { return (a + b - 1) / b; }

struct Scratch {
    float *ft, *h, *res2, *el, *er;
    unsigned *ah, *al, *bh, *bl;
    int *deg, *rowptr, *cursor, *esrc;
};

static void get_scratch(Scratch& s) {
    cudaGetSymbolAddress((void**)&s.ft, g_ft);
    cudaGetSymbolAddress((void**)&s.h, g_h);
    cudaGetSymbolAddress((void**)&s.res2, g_res2);
    cudaGetSymbolAddress((void**)&s.el, g_el);
    cudaGetSymbolAddress((void**)&s.er, g_er);
    cudaGetSymbolAddress((void**)&s.ah, g_ah);
    cudaGetSymbolAddress((void**)&s.al, g_al);
    cudaGetSymbolAddress((void**)&s.bh, g_bh);
    cudaGetSymbolAddress((void**)&s.bl, g_bl);
    cudaGetSymbolAddress((void**)&s.deg, g_deg);
    cudaGetSymbolAddress((void**)&s.rowptr, g_rowptr);
    cudaGetSymbolAddress((void**)&s.cursor, g_cursor);
    cudaGetSymbolAddress((void**)&s.esrc, g_esrc);
}

static void launch_prepack(const Scratch& s, const float* A,
                           const float* B1, const float* B2, int M) {
    int ta = NN * 64;
    prepack_A<<<divup(ta, 256), 256>>>(A, s.ah, s.al, ta);
    int nreg = (B2 != nullptr) ? 2 : 1;
    int tb = nreg * BP_REGION;
    prepack_B<<<divup(tb, 256), 256>>>(B1, B2, s.bh, s.bl, M, nreg);
}

static void launch_gemm(const Scratch& s, float* C1, int ldc1,
                        float* C2, int ldc2, int Mcols, bool dual) {
    const int smem_bytes = GEMM_SMEM_WORDS * 4;
    cudaFuncSetAttribute(gemm_bf16, cudaFuncAttributeMaxDynamicSharedMemorySize, smem_bytes);
    int gx = divup(Mcols, GBN);
    dim3 grid(dual ? 2 * gx : gx, divup(NN, GBM));
    gemm_bf16<<<grid, 256, smem_bytes>>>(s.ah, s.al, s.bh, s.bl,
                                         C1, ldc1, C2, ldc2, NN, Mcols, gx);
}

extern "C" void kernel_launch(void* const* d_in, const int* in_sizes, int n_in,
                              void* d_out, int out_size) {
    const float* x      = (const float*)d_in[0];
    const int*   src    = (const int*)d_in[1];
    const int*   dst    = (const int*)d_in[2];
    const float* W0     = (const float*)d_in[3];
    const float* al0    = (const float*)d_in[4];
    const float* ar0    = (const float*)d_in[5];
    const float* b0     = (const float*)d_in[6];
    const float* W1     = (const float*)d_in[7];
    const float* al1    = (const float*)d_in[8];
    const float* ar1    = (const float*)d_in[9];
    const float* b1     = (const float*)d_in[10];
    const float* W2     = (const float*)d_in[11];
    const float* al2    = (const float*)d_in[12];
    const float* ar2    = (const float*)d_in[13];
    const float* b2     = (const float*)d_in[14];
    const float* res_W2 = (const float*)d_in[15];
    float* out = (float*)d_out;

    Scratch s;
    get_scratch(s);

    const int N = NN, E = EE;
    const float4* ftv = (const float4*)s.ft;
    int aggGrid = divup(N, 8);

    // ---- layer 0 (gemm in profiled slot 4) ----
    zero_deg<<<divup(N, 256), 256>>>(s.deg, N);                    // 1
    launch_prepack(s, x, W0, nullptr, 128);                        // 2,3
    launch_gemm(s, s.ft, 128, nullptr, 0, 128, false);             // 4  <- profiled
    hist_dst<<<divup(E, 256), 256>>>(dst, s.deg, E);               // 5
    exscan_kernel<<<1, 1024>>>(s.deg, s.rowptr, s.cursor, N);      // 6
    fill_csr<<<divup(E, 256), 256>>>(src, dst, s.cursor, s.esrc, E);
    el_er_warp<<<divup(N * 32, 256), 256>>>(s.ft, al0, ar0, s.el, s.er, N, 64, 128);
    gat_agg_fused<<<aggGrid, 256>>>(s.rowptr, s.esrc, ftv, s.el, s.er, b0, nullptr,
                                    s.h, 128, 64, 32, 0);

    // ---- layer 1: identity residual, ELU ----
    launch_prepack(s, s.h, W1, nullptr, 128);
    launch_gemm(s, s.ft, 128, nullptr, 0, 128, false);
    el_er_warp<<<divup(N * 32, 256), 256>>>(s.ft, al1, ar1, s.el, s.er, N, 64, 128);
    gat_agg_fused<<<aggGrid, 256>>>(s.rowptr, s.esrc, ftv, s.el, s.er, b1, s.h,
                                    s.h, 128, 64, 32, 0);

    // ---- layer 2: dual GEMM (W2 -> ft stride 196, res_W2 -> res2), fused final ----
    launch_prepack(s, s.h, W2, res_W2, 194);
    launch_gemm(s, s.ft, 196, s.res2, 194, 194, true);
    el_er_warp<<<divup(N * 32, 256), 256>>>(s.ft, al2, ar2, s.el, s.er, N, 97, 196);
    gat_agg_fused<<<aggGrid, 256>>>(s.rowptr, s.esrc, ftv, s.el, s.er, b2, s.res2,
                                    out, 194, 97, 49, 2);
}

// round 11
// speedup vs baseline: 1.0878x; 1.0482x over previous
#include <cuda_runtime.h>
#include <cuda_bf16.h>
#include <math.h>

#define NN 50000
#define EE 800000
#define NEG_SLOPE 0.2f

// ---------------- scratch (no allocations allowed) ----------------
__device__ float    g_ft[NN * 196];
__device__ float    g_h[NN * 128];
__device__ float    g_res2[NN * 194];
__device__ float    g_el[NN * 2];
__device__ float    g_er[NN * 2];
__device__ unsigned g_ah[NN * 64];      // prepacked A hi (bf16x2 per kpair)
__device__ unsigned g_al[NN * 64];      // prepacked A lo
__device__ unsigned g_bh[2 * 64 * 256];
__device__ unsigned g_bl[2 * 64 * 256];
__device__ int      g_deg[NN];
__device__ int      g_rowptr[NN + 1];
__device__ int      g_cursor[NN];
__device__ int      g_esrc[EE];

#define BP_STR 256
#define BP_REGION (64 * BP_STR)

// ---------------- bf16 helpers ----------------
__device__ __forceinline__ unsigned pack_bf16x2(float x, float y) {
    __nv_bfloat162 t = __floats2bfloat162_rn(x, y);
    return *reinterpret_cast<unsigned*>(&t);
}

__device__ __forceinline__ void mma_bf16(float* c, const unsigned* a, const unsigned* b) {
    asm volatile(
        "mma.sync.aligned.m16n8k16.row.col.f32.bf16.bf16.f32 "
        "{%0,%1,%2,%3}, {%4,%5,%6,%7}, {%8,%9}, {%0,%1,%2,%3};\n"
        : "+f"(c[0]), "+f"(c[1]), "+f"(c[2]), "+f"(c[3])
        : "r"(a[0]), "r"(a[1]), "r"(a[2]), "r"(a[3]), "r"(b[0]), "r"(b[1]));
}

// ---------------- prepack kernels ----------------
__global__ void prepack_A(const float* __restrict__ A,
                          unsigned* __restrict__ ah, unsigned* __restrict__ al, int total) {
    int idx = blockIdx.x * blockDim.x + threadIdx.x;
    if (idx >= total) return;
    float2 v = *(const float2*)(A + (long)idx * 2);
    float hx = __bfloat162float(__float2bfloat16_rn(v.x));
    float hy = __bfloat162float(__float2bfloat16_rn(v.y));
    ah[idx] = pack_bf16x2(hx, hy);
    al[idx] = pack_bf16x2(v.x - hx, v.y - hy);
}

__global__ void prepack_B(const float* __restrict__ B1, const float* __restrict__ B2,
                          unsigned* __restrict__ bh, unsigned* __restrict__ bl,
                          int M, int nregions) {
    int idx = blockIdx.x * blockDim.x + threadIdx.x;
    int total = nregions * BP_REGION;
    if (idx >= total) return;
    int region = idx / BP_REGION;
    int rem = idx - region * BP_REGION;
    int kp = rem / BP_STR;
    int c = rem - kp * BP_STR;
    const float* B = region ? B2 : B1;
    float v0 = 0.f, v1 = 0.f;
    if (c < M) {
        v0 = B[(2 * kp) * M + c];
        v1 = B[(2 * kp + 1) * M + c];
    }
    float h0 = __bfloat162float(__float2bfloat16_rn(v0));
    float h1 = __bfloat162float(__float2bfloat16_rn(v1));
    bh[idx] = pack_bf16x2(h0, h1);
    bl[idx] = pack_bf16x2(v0 - h0, v1 - h1);
}

// ================= bf16x3 GEMM, 128x128 tile, 512 threads (16 warps) =================
#define GBM 128
#define GBN 128
#define A_STR 68
#define B_STR 136
#define SM_AH 0
#define SM_AL (128 * A_STR)
#define SM_BH (2 * 128 * A_STR)
#define SM_BL (2 * 128 * A_STR + 64 * B_STR)
#define GEMM_SMEM_WORDS (2 * 128 * A_STR + 2 * 64 * B_STR)   // 139264 B

__global__ void __launch_bounds__(512)
gemm_bf16(const unsigned* __restrict__ gah, const unsigned* __restrict__ gal,
          const unsigned* __restrict__ bph, const unsigned* __restrict__ bpl,
          float* __restrict__ C1, int ldc1, float* __restrict__ C2, int ldc2,
          int Nrows, int Mcols, int gx) {
    extern __shared__ unsigned smu[];
    unsigned* Ah = smu + SM_AH;
    unsigned* Al = smu + SM_AL;
    unsigned* Bh = smu + SM_BH;
    unsigned* Bl = smu + SM_BL;

    const int tid = threadIdx.x;
    const int lane = tid & 31;
    const int warp = tid >> 5;      // 0..15
    const int wm = warp & 3;        // 4 warps along M (32 rows each)
    const int wn = warp >> 2;       // 4 warps along N (32 cols each)
    const int row0 = blockIdx.y * GBM;
    const bool second = (blockIdx.x >= gx);
    const int bx = second ? (blockIdx.x - gx) : blockIdx.x;
    float* C = second ? C2 : C1;
    const int ldc = second ? ldc2 : ldc1;
    const int col0 = bx * GBN;
    const unsigned* bhs = bph + (second ? BP_REGION : 0);
    const unsigned* bls = bpl + (second ? BP_REGION : 0);

    #pragma unroll 8
    for (int i = 0; i < 16; i++) {
        int e = tid + i * 512;
        int r = e >> 6;
        int kp = e & 63;
        int gr = row0 + r;
        unsigned h = 0, l = 0;
        if (gr < Nrows) {
            h = gah[(long)gr * 64 + kp];
            l = gal[(long)gr * 64 + kp];
        }
        Ah[r * A_STR + kp] = h;
        Al[r * A_STR + kp] = l;
    }
    #pragma unroll 8
    for (int i = 0; i < 16; i++) {
        int e = tid + i * 512;
        int c = e & 127;
        int kp = e >> 7;
        Bh[kp * B_STR + c] = bhs[kp * BP_STR + col0 + c];
        Bl[kp * B_STR + c] = bls[kp * BP_STR + col0 + c];
    }
    __syncthreads();

    float acc[2][4][4];
    #pragma unroll
    for (int mt = 0; mt < 2; mt++)
        #pragma unroll
        for (int nt = 0; nt < 4; nt++)
            #pragma unroll
            for (int j = 0; j < 4; j++) acc[mt][nt][j] = 0.f;

    const int qr = lane >> 2;
    const int qc = lane & 3;

    #pragma unroll
    for (int ks = 0; ks < 8; ks++) {
        const int kg = ks * 8;
        unsigned aH[2][4], aL[2][4];
        #pragma unroll
        for (int mt = 0; mt < 2; mt++) {
            int r = wm * 32 + mt * 16 + qr;
            int b0 = r * A_STR + kg + qc;
            int b1 = (r + 8) * A_STR + kg + qc;
            aH[mt][0] = Ah[b0];     aH[mt][1] = Ah[b1];
            aH[mt][2] = Ah[b0 + 4]; aH[mt][3] = Ah[b1 + 4];
            aL[mt][0] = Al[b0];     aL[mt][1] = Al[b1];
            aL[mt][2] = Al[b0 + 4]; aL[mt][3] = Al[b1 + 4];
        }
        #pragma unroll
        for (int nt = 0; nt < 4; nt++) {
            int c = wn * 32 + nt * 8 + qr;
            int b0 = (kg + qc) * B_STR + c;
            int b1 = (kg + qc + 4) * B_STR + c;
            unsigned bH[2] = { Bh[b0], Bh[b1] };
            unsigned bL[2] = { Bl[b0], Bl[b1] };
            #pragma unroll
            for (int mt = 0; mt < 2; mt++) {
                mma_bf16(acc[mt][nt], aH[mt], bH);
                mma_bf16(acc[mt][nt], aH[mt], bL);
                mma_bf16(acc[mt][nt], aL[mt], bH);
            }
        }
    }

    #pragma unroll
    for (int mt = 0; mt < 2; mt++) {
        int r = row0 + wm * 32 + mt * 16 + qr;
        #pragma unroll
        for (int nt = 0; nt < 4; nt++) {
            int c = col0 + wn * 32 + nt * 8 + qc * 2;
            if (r < Nrows) {
                if (c < Mcols)     C[(long)r * ldc + c]     = acc[mt][nt][0];
                if (c + 1 < Mcols) C[(long)r * ldc + c + 1] = acc[mt][nt][1];
            }
            if (r + 8 < Nrows) {
                if (c < Mcols)     C[(long)(r + 8) * ldc + c]     = acc[mt][nt][2];
                if (c + 1 < Mcols) C[(long)(r + 8) * ldc + c + 1] = acc[mt][nt][3];
            }
        }
    }
}

// ---------------- CSR build ----------------
__global__ void zero_deg(int* __restrict__ deg, int n) {
    int i = blockIdx.x * blockDim.x + threadIdx.x;
    if (i < n) deg[i] = 0;
}

__global__ void hist_dst(const int* __restrict__ dst, int* __restrict__ deg, int E) {
    int e = blockIdx.x * blockDim.x + threadIdx.x;
    if (e < E) atomicAdd(&deg[dst[e]], 1);
}

__global__ void exscan_kernel(const int* __restrict__ deg, int* __restrict__ rowptr,
                              int* __restrict__ cursor, int n) {
    __shared__ int sh[1024];
    int t = threadIdx.x;
    const int CH = (n + 1023) / 1024;
    int base = t * CH;
    int sum = 0;
    for (int i = 0; i < CH; i++) {
        int idx = base + i;
        if (idx < n) sum += deg[idx];
    }
    sh[t] = sum;
    __syncthreads();
    for (int off = 1; off < 1024; off <<= 1) {
        int v = (t >= off) ? sh[t - off] : 0;
        __syncthreads();
        sh[t] += v;
        __syncthreads();
    }
    int run = (t == 0) ? 0 : sh[t - 1];
    for (int i = 0; i < CH; i++) {
        int idx = base + i;
        if (idx < n) {
            rowptr[idx] = run;
            cursor[idx] = run;
            run += deg[idx];
        }
    }
    if (t == 1023) rowptr[n] = sh[1023];
}

__global__ void fill_csr(const int* __restrict__ src, const int* __restrict__ dst,
                         int* __restrict__ cursor, int* __restrict__ esrc, int E) {
    int e = blockIdx.x * blockDim.x + threadIdx.x;
    if (e >= E) return;
    int pos = atomicAdd(&cursor[dst[e]], 1);
    esrc[pos] = src[e];
}

// ---------------- el/er: warp per node ----------------
__global__ void el_er_warp(const float* __restrict__ ft,
                           const float* __restrict__ al, const float* __restrict__ ar,
                           float* __restrict__ el, float* __restrict__ er,
                           int N, int D, int stride) {
    int warp = (blockIdx.x * blockDim.x + threadIdx.x) >> 5;
    int lane = threadIdx.x & 31;
    if (warp >= N) return;
    int F = 2 * D;
    const float* f = ft + (long)warp * stride;
    float sl0 = 0.f, sr0 = 0.f, sl1 = 0.f, sr1 = 0.f;
    for (int i = lane; i < F; i += 32) {
        float v = f[i];
        float a = al[i];
        float r = ar[i];
        if (i < D) { sl0 += v * a; sr0 += v * r; }
        else       { sl1 += v * a; sr1 += v * r; }
    }
    #pragma unroll
    for (int o = 16; o > 0; o >>= 1) {
        sl0 += __shfl_xor_sync(0xffffffff, sl0, o);
        sr0 += __shfl_xor_sync(0xffffffff, sr0, o);
        sl1 += __shfl_xor_sync(0xffffffff, sl1, o);
        sr1 += __shfl_xor_sync(0xffffffff, sr1, o);
    }
    if (lane == 0) {
        el[warp * 2]     = sl0;
        el[warp * 2 + 1] = sl1;
        er[warp * 2]     = sr0;
        er[warp * 2 + 1] = sr1;
    }
}

// ---------------- fused softmax + aggregate: warp per node ----------------
// mode 0: ELU -> out (stride F); optionally also emits prepacked bf16 hi/lo
//         (pah/pal) for the NEXT layer's GEMM A operand.
// mode 2: mean-over-heads + drop-last-node.
__global__ void __launch_bounds__(256)
gat_agg_fused(const int* __restrict__ rowptr, const int* __restrict__ esrc,
              const float4* __restrict__ ftv,
              const float* __restrict__ el, const float* __restrict__ er,
              const float* __restrict__ bias, const float* __restrict__ res,
              float* __restrict__ out,
              unsigned* __restrict__ pah, unsigned* __restrict__ pal,
              int F, int D, int stride4, int mode) {
    __shared__ float s_fin[8][194];
    const int wid = threadIdx.x >> 5;
    const int lane = threadIdx.x & 31;
    const int n = blockIdx.x * 8 + wid;
    if (n >= NN) return;

    const int start = rowptr[n], end = rowptr[n + 1];
    const float er0 = er[n * 2], er1 = er[n * 2 + 1];
    const int CHN = (F + 3) >> 2;
    const bool secondc = (lane + 32) < CHN;
    const int c0 = lane * 4;
    const int c1 = 128 + lane * 4;

    float4 a0 = make_float4(0.f, 0.f, 0.f, 0.f);
    float4 a1 = make_float4(0.f, 0.f, 0.f, 0.f);
    float accw0 = 0.f, accw1 = 0.f;

    for (int base = start; base < end; base += 32) {
        int i = base + lane;
        int s = 0;
        float e0 = 0.f, e1 = 0.f;
        if (i < end) {
            s = esrc[i];
            float v0 = el[s * 2] + er0;     v0 = (v0 > 0.f) ? v0 : NEG_SLOPE * v0;
            float v1 = el[s * 2 + 1] + er1; v1 = (v1 > 0.f) ? v1 : NEG_SLOPE * v1;
            e0 = __expf(v0);
            e1 = __expf(v1);
        }
        accw0 += e0;
        accw1 += e1;
        int cnt = min(32, end - base);
        #pragma unroll 4
        for (int j = 0; j < cnt; j++) {
            float w0 = __shfl_sync(0xffffffff, e0, j);
            float w1 = __shfl_sync(0xffffffff, e1, j);
            int sj   = __shfl_sync(0xffffffff, s, j);
            const float4* row = ftv + (long)sj * stride4;
            float4 f0 = row[lane];
            a0.x += f0.x * ((c0 + 0 < D) ? w0 : w1);
            a0.y += f0.y * ((c0 + 1 < D) ? w0 : w1);
            a0.z += f0.z * ((c0 + 2 < D) ? w0 : w1);
            a0.w += f0.w * ((c0 + 3 < D) ? w0 : w1);
            if (secondc) {
                float4 f1 = row[lane + 32];
                a1.x += f1.x * ((c1 + 0 < D) ? w0 : w1);
                a1.y += f1.y * ((c1 + 1 < D) ? w0 : w1);
                a1.z += f1.z * ((c1 + 2 < D) ? w0 : w1);
                a1.w += f1.w * ((c1 + 3 < D) ? w0 : w1);
            }
        }
    }

    #pragma unroll
    for (int o = 16; o > 0; o >>= 1) {
        accw0 += __shfl_xor_sync(0xffffffff, accw0, o);
        accw1 += __shfl_xor_sync(0xffffffff, accw1, o);
    }
    const float inv0 = (accw0 > 0.f) ? (1.f / accw0) : 0.f;
    const float inv1 = (accw1 > 0.f) ? (1.f / accw1) : 0.f;

    if (mode == 0) {
        float4 b4 = *(const float4*)(bias + c0);
        float4 r;
        r.x = a0.x * ((c0 + 0 < D) ? inv0 : inv1) + b4.x;
        r.y = a0.y * ((c0 + 1 < D) ? inv0 : inv1) + b4.y;
        r.z = a0.z * ((c0 + 2 < D) ? inv0 : inv1) + b4.z;
        r.w = a0.w * ((c0 + 3 < D) ? inv0 : inv1) + b4.w;
        if (res) {
            float4 rv = *(const float4*)(res + (long)n * F + c0);
            r.x += rv.x; r.y += rv.y; r.z += rv.z; r.w += rv.w;
        }
        r.x = (r.x > 0.f) ? r.x : (__expf(r.x) - 1.f);
        r.y = (r.y > 0.f) ? r.y : (__expf(r.y) - 1.f);
        r.z = (r.z > 0.f) ? r.z : (__expf(r.z) - 1.f);
        r.w = (r.w > 0.f) ? r.w : (__expf(r.w) - 1.f);
        *(float4*)(out + (long)n * F + c0) = r;
        if (pah) {
            // lane holds channels c0..c0+3 == kpairs 2*lane, 2*lane+1
            float hx = __bfloat162float(__float2bfloat16_rn(r.x));
            float hy = __bfloat162float(__float2bfloat16_rn(r.y));
            float hz = __bfloat162float(__float2bfloat16_rn(r.z));
            float hw = __bfloat162float(__float2bfloat16_rn(r.w));
            pah[(long)n * 64 + lane * 2]     = pack_bf16x2(hx, hy);
            pah[(long)n * 64 + lane * 2 + 1] = pack_bf16x2(hz, hw);
            pal[(long)n * 64 + lane * 2]     = pack_bf16x2(r.x - hx, r.y - hy);
            pal[(long)n * 64 + lane * 2 + 1] = pack_bf16x2(r.z - hz, r.w - hw);
        }
    } else {
        float v0[4] = {a0.x, a0.y, a0.z, a0.w};
        float v1[4] = {a1.x, a1.y, a1.z, a1.w};
        #pragma unroll
        for (int jj = 0; jj < 4; jj++) {
            int ch = c0 + jj;
            float r = v0[jj] * ((ch < D) ? inv0 : inv1) + bias[ch];
            if (res) r += res[(long)n * F + ch];
            s_fin[wid][ch] = r;
        }
        if (secondc) {
            #pragma unroll
            for (int jj = 0; jj < 4; jj++) {
                int ch = c1 + jj;
                if (ch < F) {
                    float r = v1[jj] * ((ch < D) ? inv0 : inv1) + bias[ch];
                    if (res) r += res[(long)n * F + ch];
                    s_fin[wid][ch] = r;
                }
            }
        }
        __syncwarp();
        if (n < NN - 1) {
            for (int c = lane; c < 97; c += 32)
                out[(long)n * 97 + c] = 0.5f * (s_fin[wid][c] + s_fin[wid][c + 97]);
        }
    }
}

// ---------------- host-side orchestration ----------------
static inline int divup(int a, int b) { return (a + b - 1) / b; }

struct Scratch {
    float *ft, *h, *res2, *el, *er;
    unsigned *ah, *al, *bh, *bl;
    int *deg, *rowptr, *cursor, *esrc;
};

static void get_scratch(Scratch& s) {
    cudaGetSymbolAddress((void**)&s.ft, g_ft);
    cudaGetSymbolAddress((void**)&s.h, g_h);
    cudaGetSymbolAddress((void**)&s.res2, g_res2);
    cudaGetSymbolAddress((void**)&s.el, g_el);
    cudaGetSymbolAddress((void**)&s.er, g_er);
    cudaGetSymbolAddress((void**)&s.ah, g_ah);
    cudaGetSymbolAddress((void**)&s.al, g_al);
    cudaGetSymbolAddress((void**)&s.bh, g_bh);
    cudaGetSymbolAddress((void**)&s.bl, g_bl);
    cudaGetSymbolAddress((void**)&s.deg, g_deg);
    cudaGetSymbolAddress((void**)&s.rowptr, g_rowptr);
    cudaGetSymbolAddress((void**)&s.cursor, g_cursor);
    cudaGetSymbolAddress((void**)&s.esrc, g_esrc);
}

static void launch_gemm(const Scratch& s, float* C1, int ldc1,
                        float* C2, int ldc2, int Mcols, bool dual) {
    const int smem_bytes = GEMM_SMEM_WORDS * 4;
    cudaFuncSetAttribute(gemm_bf16, cudaFuncAttributeMaxDynamicSharedMemorySize, smem_bytes);
    int gx = divup(Mcols, GBN);
    dim3 grid(dual ? 2 * gx : gx, divup(NN, GBM));
    gemm_bf16<<<grid, 512, smem_bytes>>>(s.ah, s.al, s.bh, s.bl,
                                         C1, ldc1, C2, ldc2, NN, Mcols, gx);
}

extern "C" void kernel_launch(void* const* d_in, const int* in_sizes, int n_in,
                              void* d_out, int out_size) {
    const float* x      = (const float*)d_in[0];
    const int*   src    = (const int*)d_in[1];
    const int*   dst    = (const int*)d_in[2];
    const float* W0     = (const float*)d_in[3];
    const float* al0    = (const float*)d_in[4];
    const float* ar0    = (const float*)d_in[5];
    const float* b0     = (const float*)d_in[6];
    const float* W1     = (const float*)d_in[7];
    const float* al1    = (const float*)d_in[8];
    const float* ar1    = (const float*)d_in[9];
    const float* b1     = (const float*)d_in[10];
    const float* W2     = (const float*)d_in[11];
    const float* al2    = (const float*)d_in[12];
    const float* ar2    = (const float*)d_in[13];
    const float* b2     = (const float*)d_in[14];
    const float* res_W2 = (const float*)d_in[15];
    float* out = (float*)d_out;

    Scratch s;
    get_scratch(s);

    const int N = NN, E = EE;
    const float4* ftv = (const float4*)s.ft;
    int aggGrid = divup(N, 8);

    // ---- layer 0 (gemm in profiled slot 4) ----
    zero_deg<<<divup(N, 256), 256>>>(s.deg, N);                         // 1
    prepack_A<<<divup(N * 64, 256), 256>>>(x, s.ah, s.al, N * 64);      // 2
    prepack_B<<<divup(BP_REGION, 256), 256>>>(W0, nullptr, s.bh, s.bl, 128, 1); // 3
    launch_gemm(s, s.ft, 128, nullptr, 0, 128, false);                  // 4 <- profiled
    hist_dst<<<divup(E, 256), 256>>>(dst, s.deg, E);
    exscan_kernel<<<1, 1024>>>(s.deg, s.rowptr, s.cursor, N);
    fill_csr<<<divup(E, 256), 256>>>(src, dst, s.cursor, s.esrc, E);
    el_er_warp<<<divup(N * 32, 256), 256>>>(s.ft, al0, ar0, s.el, s.er, N, 64, 128);
    gat_agg_fused<<<aggGrid, 256>>>(s.rowptr, s.esrc, ftv, s.el, s.er, b0, nullptr,
                                    s.h, s.ah, s.al, 128, 64, 32, 0);

    // ---- layer 1: identity residual, ELU (A already packed by agg0) ----
    prepack_B<<<divup(BP_REGION, 256), 256>>>(W1, nullptr, s.bh, s.bl, 128, 1);
    launch_gemm(s, s.ft, 128, nullptr, 0, 128, false);
    el_er_warp<<<divup(N * 32, 256), 256>>>(s.ft, al1, ar1, s.el, s.er, N, 64, 128);
    gat_agg_fused<<<aggGrid, 256>>>(s.rowptr, s.esrc, ftv, s.el, s.er, b1, s.h,
                                    s.h, s.ah, s.al, 128, 64, 32, 0);

    // ---- layer 2: dual GEMM (A packed by agg1), fused final ----
    prepack_B<<<divup(2 * BP_REGION, 256), 256>>>(W2, res_W2, s.bh, s.bl, 194, 2);
    launch_gemm(s, s.ft, 196, s.res2, 194, 194, true);
    el_er_warp<<<divup(N * 32, 256), 256>>>(s.ft, al2, ar2, s.el, s.er, N, 97, 196);
    gat_agg_fused<<<aggGrid, 256>>>(s.rowptr, s.esrc, ftv, s.el, s.er, b2, s.res2,
                                    out, nullptr, nullptr, 194, 97, 49, 2);
}